// round 6
// baseline (speedup 1.0000x reference)
#include <cuda_runtime.h>
#include <math.h>

#define BB 256
#define IND 512
#define OUTD 512
#define ED 256
#define DELTA_C 0.1f
#define LN_EPS_C 1e-5f

typedef unsigned long long u64;

// Scratch (device globals — no allocation allowed)
__device__ float g_Wt[IND * OUTD];         // Wt[i][o] = W[o][i]
__device__ float g_AWt[ED * OUTD];         // AWt[e][o] = attn_w[o][e]
__device__ float4 g_WM[IND * (OUTD / 2)];  // (w_lo, w_hi, m_lo, m_hi) per (i, o-pair)

// ---- packed f32x2 helpers (sm_100+; only add/mul/fma exist packed) ----
__device__ __forceinline__ u64 pack2(float lo, float hi) {
    u64 r; asm("mov.b64 %0, {%1,%2};" : "=l"(r) : "f"(lo), "f"(hi)); return r;
}
#define FMA2(d,a,b,c) asm("fma.rn.f32x2 %0,%1,%2,%3;" : "=l"(d) : "l"(a),"l"(b),"l"(c))
#define MUL2(d,a,b)   asm("mul.rn.f32x2 %0,%1,%2;"    : "=l"(d) : "l"(a),"l"(b))
#define UNPACK2(lo,hi,v) asm("mov.b64 {%0,%1}, %2;" : "=f"(lo),"=f"(hi) : "l"(v))

// ============================================================
// Kernel 1: transposes.
//   blocks [0,256):   W[o][i]  -> g_Wt[i][o]   (16x16 tiles of 32x32)
//   blocks [256,384): AW[o][e] -> g_AWt[e][o]  (16 o-tiles x 8 e-tiles)
// ============================================================
__global__ __launch_bounds__(128) void kernel_transpose(
    const float* __restrict__ W, const float* __restrict__ AW) {
    __shared__ float tile[32][33];
    const int blk = blockIdx.x;
    const int tid = threadIdx.x;
    const int tx = tid & 31, ty = tid >> 5;

    if (blk < 256) {
        int c = (blk & 15) * 32 + tx;
        int r0 = (blk >> 4) * 32;
#pragma unroll
        for (int j = 0; j < 32; j += 4)
            tile[ty + j][tx] = W[(r0 + ty + j) * IND + c];
        __syncthreads();
        int c2 = (blk >> 4) * 32 + tx;
        int r2 = (blk & 15) * 32;
#pragma unroll
        for (int j = 0; j < 32; j += 4)
            g_Wt[(r2 + ty + j) * OUTD + c2] = tile[tx][ty + j];
    } else {
        int t = blk - 256;
        int o0 = (t & 15) * 32;   // o-tile
        int e0 = (t >> 4) * 32;   // e-tile
#pragma unroll
        for (int j = 0; j < 32; j += 4)
            tile[ty + j][tx] = AW[(o0 + ty + j) * ED + e0 + tx];
        __syncthreads();
#pragma unroll
        for (int j = 0; j < 32; j += 4)
            g_AWt[(e0 + ty + j) * OUTD + o0 + tx] = tile[tx][ty + j];
    }
}

// ============================================================
// Kernel 2 (fused): scores GEMM + LayerNorm + sigmoid -> g_WM
//
// grid 128 (4 i-rows each), block 256 (thread = o-pair p, full o row).
// scores[i][o]: acc[i] packed f32x2 over (o_lo,o_hi); per e:
//   1 coalesced LDG.64 from g_AWt[e][2p] + 4 broadcast LDS.64 (pe dup)
//   + 4 FMA2.  Then block-reduces LN stats over o and writes g_WM.
// ============================================================
__global__ __launch_bounds__(256) void kernel_scores_ln(
    const float* __restrict__ PE, const float* __restrict__ AB,
    const float* __restrict__ LG, const float* __restrict__ LB) {
    __shared__ float2 pe2[4][ED];     // duplicated pairs, broadcast reads
    __shared__ float wsum[4][8], wsum2[4][8];
    __shared__ float mus[4], rss[4];

    const int tid = threadIdx.x;
    const int p = tid;                // o-pair index [0,256)
    const int i0 = blockIdx.x * 4;
    const int wid = tid >> 5, lane = tid & 31;

    // Stage pred_emb rows (duplicated for f32x2).
#pragma unroll
    for (int k = 0; k < 4; k++) {
        int idx = tid + k * 256;
        int row = idx >> 8, e = idx & 255;
        float v = PE[(i0 + row) * ED + e];
        pe2[row][e] = make_float2(v, v);
    }
    __syncthreads();

    u64 acc[4];
    const u64 z = pack2(0.f, 0.f);
#pragma unroll
    for (int ii = 0; ii < 4; ii++) acc[ii] = z;

    const u64* __restrict__ awt = (const u64*)(g_AWt + 2 * p);

#pragma unroll 1
    for (int e0 = 0; e0 < ED; e0 += 4) {
        u64 aw[4];
#pragma unroll
        for (int k = 0; k < 4; k++)
            aw[k] = awt[(u64)(e0 + k) * (OUTD / 2)];
#pragma unroll
        for (int k = 0; k < 4; k++) {
#pragma unroll
            for (int ii = 0; ii < 4; ii++) {
                u64 pev = *(const u64*)&pe2[ii][e0 + k];
                FMA2(acc[ii], pev, aw[k], acc[ii]);
            }
        }
    }

    // Add bias, unpack.
    float2 ab = *(const float2*)(AB + 2 * p);
    float slo[4], shi[4];
#pragma unroll
    for (int ii = 0; ii < 4; ii++) {
        UNPACK2(slo[ii], shi[ii], acc[ii]);
        slo[ii] += ab.x;
        shi[ii] += ab.y;
    }

    // LN stats: block reduction over all 512 o per i-row.
    float ps[4], ps2[4];
#pragma unroll
    for (int ii = 0; ii < 4; ii++) {
        ps[ii] = slo[ii] + shi[ii];
        ps2[ii] = slo[ii] * slo[ii] + shi[ii] * shi[ii];
    }
#pragma unroll
    for (int off = 16; off > 0; off >>= 1) {
#pragma unroll
        for (int ii = 0; ii < 4; ii++) {
            ps[ii]  += __shfl_xor_sync(0xffffffffu, ps[ii],  off);
            ps2[ii] += __shfl_xor_sync(0xffffffffu, ps2[ii], off);
        }
    }
    if (lane == 0) {
#pragma unroll
        for (int ii = 0; ii < 4; ii++) {
            wsum[ii][wid] = ps[ii];
            wsum2[ii][wid] = ps2[ii];
        }
    }
    __syncthreads();
    if (tid < 32) {
        int ii = tid >> 3, w = tid & 7;
        float s = wsum[ii][w], s2 = wsum2[ii][w];
#pragma unroll
        for (int off = 4; off > 0; off >>= 1) {
            s  += __shfl_xor_sync(0xffffffffu, s,  off);
            s2 += __shfl_xor_sync(0xffffffffu, s2, off);
        }
        if (w == 0) {
            float mu = s * (1.f / OUTD);
            float var = s2 * (1.f / OUTD) - mu * mu;
            mus[ii] = mu;
            rss[ii] = rsqrtf(var + LN_EPS_C);
        }
    }
    __syncthreads();

    // Epilogue: LN -> sigmoid -> g_WM float4.
    float2 gg = *(const float2*)(LG + 2 * p);
    float2 bb = *(const float2*)(LB + 2 * p);
#pragma unroll
    for (int ii = 0; ii < 4; ii++) {
        float mu = mus[ii], rs = rss[ii];
        float2 wv = *(const float2*)(g_Wt + (i0 + ii) * OUTD + 2 * p);
        float vlo = (slo[ii] - mu) * rs * gg.x + bb.x;
        float vhi = (shi[ii] - mu) * rs * gg.y + bb.y;
        float siglo = 1.f / (1.f + __expf(-vlo));
        float sighi = 1.f / (1.f + __expf(-vhi));
        float4 q;
        q.x = wv.x; q.y = wv.y;
        q.z = fabsf(wv.x) * siglo;
        q.w = fabsf(wv.y) * sighi;
        g_WM[(i0 + ii) * (OUTD / 2) + p] = q;
    }
}

// ============================================================
// Kernel 3 (main): out[b,o] = x@Wt + 0.1*(max_i t*M - sum_i t*M)
// (unchanged from round 5)
// ============================================================
#define MAIN_SMEM (4 * IND * 16)  // 32 KB

__global__ __launch_bounds__(256, 3) void kernel_main(
    const float* __restrict__ X, float* __restrict__ out) {
    extern __shared__ char smem_raw[];
    ulonglong2 (*xt)[IND] = (ulonglong2 (*)[IND])smem_raw;  // [4][512]
    float* red = (float*)smem_raw;

    const int tid = threadIdx.x;
    const int to = tid & 15;
    const int si = tid >> 4;        // [0,16), i-chunk of 32
    const int b0 = blockIdx.y * 4;

    for (int idx = tid; idx < 4 * IND; idx += 256) {
        int b = idx >> 9, i = idx & 511;
        float xv = X[(b0 + b) * IND + i];
        float tv = xv * fabsf(xv);
        xt[b][i] = make_ulonglong2(pack2(xv, xv), pack2(tv, tv));
    }
    __syncthreads();

    u64 c[4][2];
    float mxl[4][2], mxh[4][2];
    const u64 z = pack2(0.f, 0.f);
    const u64 n01 = pack2(-DELTA_C, -DELTA_C);
#pragma unroll
    for (int b = 0; b < 4; b++) {
        c[b][0] = z; c[b][1] = z;
        mxl[b][0] = -INFINITY; mxl[b][1] = -INFINITY;
        mxh[b][0] = -INFINITY; mxh[b][1] = -INFINITY;
    }

    const int ib = si * 32;
    const float4* __restrict__ base = g_WM + blockIdx.x * 32 + to;

    auto LD = [&](float4 q[2][2], int i) {
        q[0][0] = __ldg(base + i * (OUTD / 2));
        q[0][1] = __ldg(base + i * (OUTD / 2) + 16);
        q[1][0] = __ldg(base + (i + 1) * (OUTD / 2));
        q[1][1] = __ldg(base + (i + 1) * (OUTD / 2) + 16);
    };
    auto COMP = [&](float4 q[2][2], int i) {
#pragma unroll
        for (int k = 0; k < 2; k++) {
            u64 w2a = pack2(q[k][0].x, q[k][0].y);
            u64 m2a = pack2(q[k][0].z, q[k][0].w);
            u64 w2b = pack2(q[k][1].x, q[k][1].y);
            u64 m2b = pack2(q[k][1].z, q[k][1].w);
#pragma unroll
            for (int b = 0; b < 4; b++) {
                ulonglong2 v = xt[b][i + k];
                FMA2(c[b][0], v.x, w2a, c[b][0]);
                u64 pa; MUL2(pa, v.y, m2a);
                FMA2(c[b][0], pa, n01, c[b][0]);
                float palo, pahi; UNPACK2(palo, pahi, pa);
                mxl[b][0] = fmaxf(mxl[b][0], palo);
                mxh[b][0] = fmaxf(mxh[b][0], pahi);
                FMA2(c[b][1], v.x, w2b, c[b][1]);
                u64 pb; MUL2(pb, v.y, m2b);
                FMA2(c[b][1], pb, n01, c[b][1]);
                float pblo, pbhi; UNPACK2(pblo, pbhi, pb);
                mxl[b][1] = fmaxf(mxl[b][1], pblo);
                mxh[b][1] = fmaxf(mxh[b][1], pbhi);
            }
        }
    };

    float4 qc[2][2], qn[2][2];
    LD(qc, ib);
#pragma unroll 1
    for (int g = 0; g < 8; g++) {
        LD(qn, ib + 4 * g + 2);
        COMP(qc, ib + 4 * g);
        if (g < 7) LD(qc, ib + 4 * g + 4);
        COMP(qn, ib + 4 * g + 2);
    }

    __syncthreads();

#define RIDX(k, b, j, s, t) ((((((k) * 4 + (b)) * 2 + (j)) * 16 + (s)) * 16) + (t))
#pragma unroll
    for (int b = 0; b < 4; b++) {
#pragma unroll
        for (int j = 0; j < 2; j++) {
            float clo, chi;
            UNPACK2(clo, chi, c[b][j]);
            red[RIDX(0, b, j, si, to)] = clo;
            red[RIDX(1, b, j, si, to)] = chi;
            red[RIDX(2, b, j, si, to)] = mxl[b][j];
            red[RIDX(3, b, j, si, to)] = mxh[b][j];
        }
    }
    __syncthreads();

    if (tid < 128) {
        const int b2 = tid >> 5;
        const int pl = tid & 31;
        const int j2 = pl >> 4;
        const int to2 = pl & 15;
        float slo = 0.f, shi = 0.f, Mlo = -INFINITY, Mhi = -INFINITY;
#pragma unroll
        for (int s = 0; s < 16; s++) {
            slo += red[RIDX(0, b2, j2, s, to2)];
            shi += red[RIDX(1, b2, j2, s, to2)];
            Mlo = fmaxf(Mlo, red[RIDX(2, b2, j2, s, to2)]);
            Mhi = fmaxf(Mhi, red[RIDX(3, b2, j2, s, to2)]);
        }
        float2 r;
        r.x = slo + DELTA_C * Mlo;
        r.y = shi + DELTA_C * Mhi;
        *(float2*)(out + (b0 + b2) * OUTD + blockIdx.x * 64 + pl * 2) = r;
    }
#undef RIDX
}

// ============================================================
extern "C" void kernel_launch(void* const* d_in, const int* in_sizes, int n_in,
                              void* d_out, int out_size) {
    const float* x  = (const float*)d_in[0];
    const float* w  = (const float*)d_in[1];
    const float* pe = (const float*)d_in[2];
    const float* aw = (const float*)d_in[3];
    const float* ab = (const float*)d_in[4];
    const float* lg = (const float*)d_in[5];
    const float* lb = (const float*)d_in[6];
    float* out = (float*)d_out;

    kernel_transpose<<<384, 128>>>(w, aw);
    kernel_scores_ln<<<128, 256>>>(pe, ab, lg, lb);
    kernel_main<<<dim3(8, 64), 256, MAIN_SMEM>>>(x, out);
}

// round 7
// speedup vs baseline: 1.4883x; 1.4883x over previous
#include <cuda_runtime.h>
#include <math.h>

#define BB 256
#define IND 512
#define OUTD 512
#define ED 256
#define DELTA_C 0.1f
#define LN_EPS_C 1e-5f

typedef unsigned long long u64;

// Scratch (device globals — no allocation allowed)
__device__ float g_Wt[IND * OUTD];         // Wt[i][o] = W[o][i]
__device__ float g_AWt[ED * OUTD];         // AWt[e][o] = attn_w[o][e]
__device__ u64 g_PE2[ED * IND];            // PE2[e][i] = (PE[i][e], PE[i][e])
__device__ float g_scores[IND * OUTD];     // scores[i][o]
__device__ float4 g_WM[IND * (OUTD / 2)];  // (w_lo, w_hi, m_lo, m_hi)

// ---- packed f32x2 helpers (sm_100+; only add/mul/fma exist packed) ----
__device__ __forceinline__ u64 pack2(float lo, float hi) {
    u64 r; asm("mov.b64 %0, {%1,%2};" : "=l"(r) : "f"(lo), "f"(hi)); return r;
}
#define FMA2(d,a,b,c) asm("fma.rn.f32x2 %0,%1,%2,%3;" : "=l"(d) : "l"(a),"l"(b),"l"(c))
#define MUL2(d,a,b)   asm("mul.rn.f32x2 %0,%1,%2;"    : "=l"(d) : "l"(a),"l"(b))
#define UNPACK2(lo,hi,v) asm("mov.b64 {%0,%1}, %2;" : "=f"(lo),"=f"(hi) : "l"(v))

// ============================================================
// Kernel 1: transposes / relayouts.
//   blocks [0,256):   W[o][i]  -> g_Wt[i][o]
//   blocks [256,384): AW[o][e] -> g_AWt[e][o]
//   blocks [384,512): PE[i][e] -> g_PE2[e][i] (duplicated u64)
// ============================================================
__global__ __launch_bounds__(128) void kernel_prep(
    const float* __restrict__ W, const float* __restrict__ AW,
    const float* __restrict__ PE) {
    __shared__ float tile[32][33];
    const int blk = blockIdx.x;
    const int tid = threadIdx.x;
    const int tx = tid & 31, ty = tid >> 5;

    if (blk < 256) {
        int c = (blk & 15) * 32 + tx;
        int r0 = (blk >> 4) * 32;
#pragma unroll
        for (int j = 0; j < 32; j += 4)
            tile[ty + j][tx] = W[(r0 + ty + j) * IND + c];
        __syncthreads();
        int c2 = (blk >> 4) * 32 + tx;
        int r2 = (blk & 15) * 32;
#pragma unroll
        for (int j = 0; j < 32; j += 4)
            g_Wt[(r2 + ty + j) * OUTD + c2] = tile[tx][ty + j];
    } else if (blk < 384) {
        int t = blk - 256;
        int o0 = (t & 15) * 32;
        int e0 = (t >> 4) * 32;
#pragma unroll
        for (int j = 0; j < 32; j += 4)
            tile[ty + j][tx] = AW[(o0 + ty + j) * ED + e0 + tx];
        __syncthreads();
#pragma unroll
        for (int j = 0; j < 32; j += 4)
            g_AWt[(e0 + ty + j) * OUTD + o0 + tx] = tile[tx][ty + j];
    } else {
        int t = blk - 384;
        int i0 = (t & 15) * 32;
        int e0 = (t >> 4) * 32;
#pragma unroll
        for (int j = 0; j < 32; j += 4)
            tile[ty + j][tx] = PE[(i0 + ty + j) * ED + e0 + tx];
        __syncthreads();
#pragma unroll
        for (int j = 0; j < 32; j += 4) {
            float v = tile[tx][ty + j];
            g_PE2[(e0 + ty + j) * IND + i0 + tx] = pack2(v, v);
        }
    }
}

// ============================================================
// Kernel 2: tiled scores GEMM. scores[i][o] = AB[o] + sum_e PE[i][e]*AWt[e][o]
//
// grid 128 = (8 o-tiles of 64) x (16 i-tiles of 32), block 128.
// Thread (ti=tid>>4, to=tid&15): 4 i x 2 o-pairs, 8 u64 accumulators.
// K staged in 32-e chunks, double-buffered smem (padded rows), LDG for
// next chunk issued before compute of current chunk.
// ============================================================
__global__ __launch_bounds__(128) void kernel_scores(
    const float* __restrict__ AB) {
    __shared__ float awb[2][32][68];   // [buf][e][o_local], padded
    __shared__ u64 peb[2][32][34];     // [buf][e][i_local] dup, padded

    const int tid = threadIdx.x;
    const int to = tid & 15;           // floats o0 + 4*to .. +3
    const int ti = tid >> 4;           // i0 + 4*ti .. +3
    const int o0 = (blockIdx.x & 7) * 64;
    const int i0 = (blockIdx.x >> 3) * 32;

    const int sr = tid >> 4;           // staging row base [0,8)
    const int sc = tid & 15;           // staging col

    u64 acc[4][2];
    const u64 z = pack2(0.f, 0.f);
#pragma unroll
    for (int ii = 0; ii < 4; ii++) { acc[ii][0] = z; acc[ii][1] = z; }

    float4 qa[4];
    ulonglong2 qp[4];

    auto LDGC = [&](int e0) {
#pragma unroll
        for (int k = 0; k < 4; k++) {
            int row = sr + k * 8;
            qa[k] = *(const float4*)(g_AWt + (e0 + row) * OUTD + o0 + sc * 4);
            qp[k] = *(const ulonglong2*)(g_PE2 + (e0 + row) * IND + i0 + sc * 2);
        }
    };
    auto STSC = [&](int buf) {
#pragma unroll
        for (int k = 0; k < 4; k++) {
            int row = sr + k * 8;
            *(float4*)&awb[buf][row][sc * 4] = qa[k];
            *(ulonglong2*)&peb[buf][row][sc * 2] = qp[k];
        }
    };
    auto COMPUTE = [&](int buf) {
#pragma unroll 4
        for (int e = 0; e < 32; e++) {
            ulonglong2 a = *(const ulonglong2*)&awb[buf][e][4 * to];
            ulonglong2 p01 = *(const ulonglong2*)&peb[buf][e][4 * ti];
            ulonglong2 p23 = *(const ulonglong2*)&peb[buf][e][4 * ti + 2];
            FMA2(acc[0][0], p01.x, a.x, acc[0][0]);
            FMA2(acc[0][1], p01.x, a.y, acc[0][1]);
            FMA2(acc[1][0], p01.y, a.x, acc[1][0]);
            FMA2(acc[1][1], p01.y, a.y, acc[1][1]);
            FMA2(acc[2][0], p23.x, a.x, acc[2][0]);
            FMA2(acc[2][1], p23.x, a.y, acc[2][1]);
            FMA2(acc[3][0], p23.y, a.x, acc[3][0]);
            FMA2(acc[3][1], p23.y, a.y, acc[3][1]);
        }
    };

    LDGC(0);
    STSC(0);
    __syncthreads();
#pragma unroll 1
    for (int c = 0; c < 8; c++) {
        if (c < 7) LDGC(32 * (c + 1));
        COMPUTE(c & 1);
        if (c < 7) {
            STSC((c + 1) & 1);
            __syncthreads();
        }
    }

    float4 bb = *(const float4*)(AB + o0 + 4 * to);
#pragma unroll
    for (int ii = 0; ii < 4; ii++) {
        float f0, f1, f2, f3;
        UNPACK2(f0, f1, acc[ii][0]);
        UNPACK2(f2, f3, acc[ii][1]);
        float4 o4;
        o4.x = f0 + bb.x; o4.y = f1 + bb.y;
        o4.z = f2 + bb.z; o4.w = f3 + bb.w;
        *(float4*)(g_scores + (i0 + 4 * ti + ii) * OUTD + o0 + 4 * to) = o4;
    }
}

// ============================================================
// Kernel 3: LayerNorm -> sigmoid -> write interleaved g_WM float4
// ============================================================
__global__ __launch_bounds__(128) void kernel_lnwm(
    const float* __restrict__ LG, const float* __restrict__ LB) {
    const int tid = threadIdx.x;
    const int i0 = blockIdx.x * 4;
    const int w = tid >> 5, lane = tid & 31;
    __shared__ float mus[4], rss[4];

    {
        const float* row = g_scores + (i0 + w) * OUTD;
        float s = 0.f, s2 = 0.f;
#pragma unroll
        for (int k = 0; k < 16; k++) {
            float v = row[lane + 32 * k];
            s += v; s2 += v * v;
        }
#pragma unroll
        for (int off = 16; off > 0; off >>= 1) {
            s  += __shfl_xor_sync(0xffffffffu, s,  off);
            s2 += __shfl_xor_sync(0xffffffffu, s2, off);
        }
        if (lane == 0) {
            float mu = s * (1.f / OUTD);
            float var = s2 * (1.f / OUTD) - mu * mu;
            mus[w] = mu;
            rss[w] = rsqrtf(var + LN_EPS_C);
        }
    }
    __syncthreads();
#pragma unroll
    for (int ii = 0; ii < 4; ii++) {
        float mu = mus[ii], rs = rss[ii];
        const int i = i0 + ii;
#pragma unroll
        for (int j = 0; j < 2; j++) {
            int p = tid + j * 128;  // o-pair index [0,256)
            float2 s2v = *(const float2*)(g_scores + i * OUTD + 2 * p);
            float2 w2v = *(const float2*)(g_Wt + i * OUTD + 2 * p);
            float glo = LG[2 * p],     blo = LB[2 * p];
            float ghi = LG[2 * p + 1], bhi = LB[2 * p + 1];
            float vlo = (s2v.x - mu) * rs * glo + blo;
            float vhi = (s2v.y - mu) * rs * ghi + bhi;
            float siglo = 1.f / (1.f + __expf(-vlo));
            float sighi = 1.f / (1.f + __expf(-vhi));
            float4 q;
            q.x = w2v.x; q.y = w2v.y;
            q.z = fabsf(w2v.x) * siglo;
            q.w = fabsf(w2v.y) * sighi;
            g_WM[i * (OUTD / 2) + p] = q;
        }
    }
}

// ============================================================
// Kernel 4 (main): out[b,o] = x@Wt + 0.1*(max_i t*M - sum_i t*M)
// (unchanged)
// ============================================================
#define MAIN_SMEM (4 * IND * 16)  // 32 KB

__global__ __launch_bounds__(256, 3) void kernel_main(
    const float* __restrict__ X, float* __restrict__ out) {
    extern __shared__ char smem_raw[];
    ulonglong2 (*xt)[IND] = (ulonglong2 (*)[IND])smem_raw;  // [4][512]
    float* red = (float*)smem_raw;

    const int tid = threadIdx.x;
    const int to = tid & 15;
    const int si = tid >> 4;        // [0,16), i-chunk of 32
    const int b0 = blockIdx.y * 4;

    for (int idx = tid; idx < 4 * IND; idx += 256) {
        int b = idx >> 9, i = idx & 511;
        float xv = X[(b0 + b) * IND + i];
        float tv = xv * fabsf(xv);
        xt[b][i] = make_ulonglong2(pack2(xv, xv), pack2(tv, tv));
    }
    __syncthreads();

    u64 c[4][2];
    float mxl[4][2], mxh[4][2];
    const u64 z = pack2(0.f, 0.f);
    const u64 n01 = pack2(-DELTA_C, -DELTA_C);
#pragma unroll
    for (int b = 0; b < 4; b++) {
        c[b][0] = z; c[b][1] = z;
        mxl[b][0] = -INFINITY; mxl[b][1] = -INFINITY;
        mxh[b][0] = -INFINITY; mxh[b][1] = -INFINITY;
    }

    const int ib = si * 32;
    const float4* __restrict__ base = g_WM + blockIdx.x * 32 + to;

    auto LD = [&](float4 q[2][2], int i) {
        q[0][0] = __ldg(base + i * (OUTD / 2));
        q[0][1] = __ldg(base + i * (OUTD / 2) + 16);
        q[1][0] = __ldg(base + (i + 1) * (OUTD / 2));
        q[1][1] = __ldg(base + (i + 1) * (OUTD / 2) + 16);
    };
    auto COMP = [&](float4 q[2][2], int i) {
#pragma unroll
        for (int k = 0; k < 2; k++) {
            u64 w2a = pack2(q[k][0].x, q[k][0].y);
            u64 m2a = pack2(q[k][0].z, q[k][0].w);
            u64 w2b = pack2(q[k][1].x, q[k][1].y);
            u64 m2b = pack2(q[k][1].z, q[k][1].w);
#pragma unroll
            for (int b = 0; b < 4; b++) {
                ulonglong2 v = xt[b][i + k];
                FMA2(c[b][0], v.x, w2a, c[b][0]);
                u64 pa; MUL2(pa, v.y, m2a);
                FMA2(c[b][0], pa, n01, c[b][0]);
                float palo, pahi; UNPACK2(palo, pahi, pa);
                mxl[b][0] = fmaxf(mxl[b][0], palo);
                mxh[b][0] = fmaxf(mxh[b][0], pahi);
                FMA2(c[b][1], v.x, w2b, c[b][1]);
                u64 pb; MUL2(pb, v.y, m2b);
                FMA2(c[b][1], pb, n01, c[b][1]);
                float pblo, pbhi; UNPACK2(pblo, pbhi, pb);
                mxl[b][1] = fmaxf(mxl[b][1], pblo);
                mxh[b][1] = fmaxf(mxh[b][1], pbhi);
            }
        }
    };

    float4 qc[2][2], qn[2][2];
    LD(qc, ib);
#pragma unroll 1
    for (int g = 0; g < 8; g++) {
        LD(qn, ib + 4 * g + 2);
        COMP(qc, ib + 4 * g);
        if (g < 7) LD(qc, ib + 4 * g + 4);
        COMP(qn, ib + 4 * g + 2);
    }

    __syncthreads();

#define RIDX(k, b, j, s, t) ((((((k) * 4 + (b)) * 2 + (j)) * 16 + (s)) * 16) + (t))
#pragma unroll
    for (int b = 0; b < 4; b++) {
#pragma unroll
        for (int j = 0; j < 2; j++) {
            float clo, chi;
            UNPACK2(clo, chi, c[b][j]);
            red[RIDX(0, b, j, si, to)] = clo;
            red[RIDX(1, b, j, si, to)] = chi;
            red[RIDX(2, b, j, si, to)] = mxl[b][j];
            red[RIDX(3, b, j, si, to)] = mxh[b][j];
        }
    }
    __syncthreads();

    if (tid < 128) {
        const int b2 = tid >> 5;
        const int pl = tid & 31;
        const int j2 = pl >> 4;
        const int to2 = pl & 15;
        float slo = 0.f, shi = 0.f, Mlo = -INFINITY, Mhi = -INFINITY;
#pragma unroll
        for (int s = 0; s < 16; s++) {
            slo += red[RIDX(0, b2, j2, s, to2)];
            shi += red[RIDX(1, b2, j2, s, to2)];
            Mlo = fmaxf(Mlo, red[RIDX(2, b2, j2, s, to2)]);
            Mhi = fmaxf(Mhi, red[RIDX(3, b2, j2, s, to2)]);
        }
        float2 r;
        r.x = slo + DELTA_C * Mlo;
        r.y = shi + DELTA_C * Mhi;
        *(float2*)(out + (b0 + b2) * OUTD + blockIdx.x * 64 + pl * 2) = r;
    }
#undef RIDX
}

// ============================================================
extern "C" void kernel_launch(void* const* d_in, const int* in_sizes, int n_in,
                              void* d_out, int out_size) {
    const float* x  = (const float*)d_in[0];
    const float* w  = (const float*)d_in[1];
    const float* pe = (const float*)d_in[2];
    const float* aw = (const float*)d_in[3];
    const float* ab = (const float*)d_in[4];
    const float* lg = (const float*)d_in[5];
    const float* lb = (const float*)d_in[6];
    float* out = (float*)d_out;

    kernel_prep<<<512, 128>>>(w, aw, pe);
    kernel_scores<<<128, 128>>>(ab);
    kernel_lnwm<<<128, 128>>>(lg, lb);
    kernel_main<<<dim3(8, 64), 256, MAIN_SMEM>>>(x, out);
}